// round 1
// baseline (speedup 1.0000x reference)
#include <cuda_runtime.h>
#include <cuda_bf16.h>

#define N_USERS     6040
#define NUM_INPUTS  9992          // 6040 + 3952
#define FACT_NUM    16
#define BATCH       4194304
#define RATING_THRESH 3

#define TPB    512
#define BLOCKS 592                // 148 SMs * 4

// Batch-independent scalar: 0.5 * sum(sum_emb^2 - sum_sq) + linear_b
__device__ float g_const;

__global__ void fm_precompute(const float* __restrict__ emb,
                              const float* __restrict__ bias) {
    if (threadIdx.x == 0 && blockIdx.x == 0) {
        const float c0 = (float)(NUM_INPUTS - 2);
        const float c1 = 2.0f;
        float acc = 0.0f;
        #pragma unroll
        for (int k = 0; k < FACT_NUM; ++k) {
            float e0 = emb[k];
            float e1 = emb[FACT_NUM + k];
            float se = c0 * e0 + c1 * e1;
            float sq = c0 * e0 * e0 + c1 * e1 * e1;
            acc += se * se - sq;
        }
        g_const = 0.5f * acc + bias[0];
    }
}

__device__ __forceinline__ float fast_sigmoid(float z) {
    // Saturation fast path: avoids MUFU entirely when |z| large
    // (here interaction ~ 1e9, so every row takes the fast path).
    if (z > 10.0f)  return 1.0f;
    if (z < -10.0f) return 0.0f;
    return 1.0f / (1.0f + __expf(-z));
}

__global__ __launch_bounds__(TPB)
void fm_main(const int4* __restrict__ x4,
             const float* __restrict__ w,
             float* __restrict__ out) {
    // Stage the 40KB linear_w table in shared memory: random gathers
    // through smem (avg ~3-way bank conflict) instead of L1tex wavefront storm.
    __shared__ float sw[NUM_INPUTS];
    for (int i = threadIdx.x; i < NUM_INPUTS; i += TPB)
        sw[i] = w[i];
    const float K = g_const;
    __syncthreads();

    float4* __restrict__ o_out = (float4*)out;
    float4* __restrict__ r_out = (float4*)(out + BATCH);

    const int ngroups = BATCH / 4;  // each group = 4 rows = 3 int4
    for (int g = blockIdx.x * TPB + threadIdx.x; g < ngroups;
         g += gridDim.x * TPB) {
        // rows 4g..4g+3 occupy ints [12g, 12g+12):
        // a=(u0,m0,r0,u1) b=(m1,r1,u2,m2) c=(r2,u3,m3,r3)
        int4 a = x4[3 * g + 0];
        int4 b = x4[3 * g + 1];
        int4 c = x4[3 * g + 2];

        float l0 = sw[a.x] + sw[N_USERS + a.y] + K;
        float l1 = sw[a.w] + sw[N_USERS + b.x] + K;
        float l2 = sw[b.z] + sw[N_USERS + b.w] + K;
        float l3 = sw[c.y] + sw[N_USERS + c.z] + K;

        float4 o, r;
        o.x = fast_sigmoid(l0);
        o.y = fast_sigmoid(l1);
        o.z = fast_sigmoid(l2);
        o.w = fast_sigmoid(l3);
        r.x = (a.z >= RATING_THRESH) ? 1.0f : 0.0f;
        r.y = (b.y >= RATING_THRESH) ? 1.0f : 0.0f;
        r.z = (c.x >= RATING_THRESH) ? 1.0f : 0.0f;
        r.w = (c.w >= RATING_THRESH) ? 1.0f : 0.0f;

        o_out[g] = o;
        r_out[g] = r;
    }
}

extern "C" void kernel_launch(void* const* d_in, const int* in_sizes, int n_in,
                              void* d_out, int out_size) {
    const int*   x       = (const int*)d_in[0];     // (BATCH, 3) int32
    const float* emb     = (const float*)d_in[1];   // (9992, 16) f32
    const float* lw      = (const float*)d_in[2];   // (1, 9992) f32
    const float* lb      = (const float*)d_in[3];   // (1,) f32
    float*       out     = (float*)d_out;           // [out(4M) | recommended(4M)]

    fm_precompute<<<1, 32>>>(emb, lb);
    fm_main<<<BLOCKS, TPB>>>((const int4*)x, lw, out);
    (void)in_sizes; (void)n_in; (void)out_size;
}

// round 2
// speedup vs baseline: 1.0277x; 1.0277x over previous
#include <cuda_runtime.h>
#include <cuda_bf16.h>
#include <math_constants.h>

#define N_USERS       6040
#define NUM_INPUTS    9992          // 6040 + 3952
#define FACT_NUM      16
#define BATCH         4194304
#define NGROUPS       (BATCH / 4)   // 1048576 groups of 4 rows
#define RATING_THRESH 3

#define TPB     512
#define BLOCKS  512                 // 512*512 = 262144 threads; 4 groups/thread exactly

// g_K = interaction + bias; g_mode: 0=general, 1=all outputs 1.0f, 2=all 0.0f
__device__ float g_K;
__device__ int   g_mode;

__global__ __launch_bounds__(TPB)
void fm_precompute(const float* __restrict__ emb,
                   const float* __restrict__ w,
                   const float* __restrict__ bias) {
    __shared__ float smin[TPB];
    __shared__ float smax[TPB];
    int tid = threadIdx.x;

    float mn = CUDART_INF_F, mx = -CUDART_INF_F;
    for (int i = tid; i < NUM_INPUTS; i += TPB) {
        float v = w[i];
        mn = fminf(mn, v);
        mx = fmaxf(mx, v);
    }
    smin[tid] = mn; smax[tid] = mx;
    __syncthreads();
    for (int s = TPB / 2; s > 0; s >>= 1) {
        if (tid < s) {
            smin[tid] = fminf(smin[tid], smin[tid + s]);
            smax[tid] = fmaxf(smax[tid], smax[tid + s]);
        }
        __syncthreads();
    }

    if (tid == 0) {
        const float c0 = (float)(NUM_INPUTS - 2);
        const float c1 = 2.0f;
        float acc = 0.0f;
        #pragma unroll
        for (int k = 0; k < FACT_NUM; ++k) {
            float e0 = emb[k];
            float e1 = emb[FACT_NUM + k];
            float se = c0 * e0 + c1 * e1;
            float sq = c0 * e0 * e0 + c1 * e1 * e1;
            acc += se * se - sq;
        }
        float K = 0.5f * acc + bias[0];
        g_K = K;
        // sigmoid(z) rounds to exactly 1.0f for z>17 (and to 0.0f for z<-88);
        // use 20 / -25 with margin. Linear part bounded by [2*wmin, 2*wmax].
        int mode = 0;
        if (K + 2.0f * smin[0] > 20.0f)       mode = 1;  // saturated high
        else if (K + 2.0f * smax[0] < -25.0f) mode = 2;  // saturated low
        g_mode = mode;
    }
}

__device__ __forceinline__ float fast_sigmoid(float z) {
    if (z > 10.0f)  return 1.0f;
    if (z < -10.0f) return 0.0f;
    return 1.0f / (1.0f + __expf(-z));
}

// groups 4g..: ints [12g,12g+12): a=(u0,m0,r0,u1) b=(m1,r1,u2,m2) c=(r2,u3,m3,r3)
__device__ __forceinline__ float4 rec4(const int4& a, const int4& b, const int4& c) {
    float4 r;
    r.x = (a.z >= RATING_THRESH) ? 1.0f : 0.0f;
    r.y = (b.y >= RATING_THRESH) ? 1.0f : 0.0f;
    r.z = (c.x >= RATING_THRESH) ? 1.0f : 0.0f;
    r.w = (c.w >= RATING_THRESH) ? 1.0f : 0.0f;
    return r;
}

__global__ __launch_bounds__(TPB)
void fm_main(const int4* __restrict__ x4,
             const float* __restrict__ w,
             float* __restrict__ out) {
    const int mode = g_mode;
    float4* __restrict__ o_out = (float4*)out;
    float4* __restrict__ r_out = (float4*)(out + BATCH);

    if (mode != 0) {
        // ---- Saturated fast path: no table, no smem, no MUFU ----
        const float ov = (mode == 1) ? 1.0f : 0.0f;
        const float4 oc = make_float4(ov, ov, ov, ov);
        const int stride = BLOCKS * TPB;                 // 262144
        const int base   = blockIdx.x * TPB + threadIdx.x;
        // NGROUPS / stride == 4 exactly: two unroll-2 chunks, MLP=6 each.
        #pragma unroll
        for (int chunk = 0; chunk < 2; ++chunk) {
            const int gA = base + (2 * chunk + 0) * stride;
            const int gB = base + (2 * chunk + 1) * stride;
            int4 a0 = x4[3 * gA + 0];
            int4 b0 = x4[3 * gA + 1];
            int4 c0 = x4[3 * gA + 2];
            int4 a1 = x4[3 * gB + 0];
            int4 b1 = x4[3 * gB + 1];
            int4 c1 = x4[3 * gB + 2];
            o_out[gA] = oc;
            o_out[gB] = oc;
            r_out[gA] = rec4(a0, b0, c0);
            r_out[gB] = rec4(a1, b1, c1);
        }
        return;
    }

    // ---- General fallback: smem-staged table gather ----
    __shared__ float sw[NUM_INPUTS];
    for (int i = threadIdx.x; i < NUM_INPUTS; i += TPB)
        sw[i] = w[i];
    const float K = g_K;
    __syncthreads();

    for (int g = blockIdx.x * TPB + threadIdx.x; g < NGROUPS;
         g += gridDim.x * TPB) {
        int4 a = x4[3 * g + 0];
        int4 b = x4[3 * g + 1];
        int4 c = x4[3 * g + 2];

        float4 o;
        o.x = fast_sigmoid(sw[a.x] + sw[N_USERS + a.y] + K);
        o.y = fast_sigmoid(sw[a.w] + sw[N_USERS + b.x] + K);
        o.z = fast_sigmoid(sw[b.z] + sw[N_USERS + b.w] + K);
        o.w = fast_sigmoid(sw[c.y] + sw[N_USERS + c.z] + K);

        o_out[g] = o;
        r_out[g] = rec4(a, b, c);
    }
}

extern "C" void kernel_launch(void* const* d_in, const int* in_sizes, int n_in,
                              void* d_out, int out_size) {
    const int*   x   = (const int*)d_in[0];     // (BATCH, 3) int32
    const float* emb = (const float*)d_in[1];   // (9992, 16) f32
    const float* lw  = (const float*)d_in[2];   // (1, 9992) f32
    const float* lb  = (const float*)d_in[3];   // (1,) f32
    float*       out = (float*)d_out;           // [out(4M) | recommended(4M)]

    fm_precompute<<<1, TPB>>>(emb, lw, lb);
    fm_main<<<BLOCKS, TPB>>>((const int4*)x, lw, out);
    (void)in_sizes; (void)n_in; (void)out_size;
}